// round 2
// baseline (speedup 1.0000x reference)
#include <cuda_runtime.h>
#include <cuda_bf16.h>

// Problem constants (dataset: N_NODES=1e6, N_EDGES=32e6)
#define MAX_NODES 1000000

// Scratch aggregation buffers (allocation-free rule -> __device__ globals)
__device__ float g_agg1[MAX_NODES];
__device__ float g_agg2[MAX_NODES];

// ---------------------------------------------------------------------------
// Kernel 1: zero both aggregation buffers (vectorized float4)
// ---------------------------------------------------------------------------
__global__ void zero_kernel(int n) {
    int i = blockIdx.x * blockDim.x + threadIdx.x;
    int stride = gridDim.x * blockDim.x;
    float4* a1 = reinterpret_cast<float4*>(g_agg1);
    float4* a2 = reinterpret_cast<float4*>(g_agg2);
    int n4 = n >> 2;
    for (int j = i; j < n4; j += stride) {
        a1[j] = make_float4(0.f, 0.f, 0.f, 0.f);
        a2[j] = make_float4(0.f, 0.f, 0.f, 0.f);
    }
    // tail
    for (int j = (n4 << 2) + i; j < n; j += stride) {
        g_agg1[j] = 0.0f;
        g_agg2[j] = 0.0f;
    }
}

// ---------------------------------------------------------------------------
// Scatter-add pass (edge_index is INT32 — JAX x64-disabled downcasts int64):
//   RELU_W == false:  agg[dst] += vals[src]               (pass 1, vals = x)
//   RELU_W == true :  agg[dst] += max(vals[src]*w, 0)     (pass 2, vals = agg1)
// int4 vector loads: 4 edges per thread per iteration.
// ---------------------------------------------------------------------------
template <bool RELU_W>
__global__ void scatter_kernel(const int* __restrict__ src,
                               const int* __restrict__ dst,
                               const float* __restrict__ vals,
                               const float* __restrict__ wptr,
                               float* __restrict__ agg,
                               int n_edges) {
    const float w = RELU_W ? __ldg(wptr) : 0.0f;

    int tid = blockIdx.x * blockDim.x + threadIdx.x;
    int stride = gridDim.x * blockDim.x;

    const int4* src4 = reinterpret_cast<const int4*>(src);
    const int4* dst4 = reinterpret_cast<const int4*>(dst);

    int n_quads = n_edges >> 2;
    for (int i = tid; i < n_quads; i += stride) {
        int4 s = src4[i];
        int4 d = dst4[i];

        float v0 = __ldg(&vals[s.x]);
        float v1 = __ldg(&vals[s.y]);
        float v2 = __ldg(&vals[s.z]);
        float v3 = __ldg(&vals[s.w]);
        if (RELU_W) {
            v0 = fmaxf(v0 * w, 0.0f);
            v1 = fmaxf(v1 * w, 0.0f);
            v2 = fmaxf(v2 * w, 0.0f);
            v3 = fmaxf(v3 * w, 0.0f);
        }
        atomicAdd(&agg[d.x], v0);
        atomicAdd(&agg[d.y], v1);
        atomicAdd(&agg[d.z], v2);
        atomicAdd(&agg[d.w], v3);
    }

    // tail (n_edges not divisible by 4)
    for (int e = (n_quads << 2) + tid; e < n_edges; e += stride) {
        int s = src[e];
        int d = dst[e];
        float t = __ldg(&vals[s]);
        if (RELU_W) t = fmaxf(t * w, 0.0f);
        atomicAdd(&agg[d], t);
    }
}

// ---------------------------------------------------------------------------
// Epilogue: out[i] = sigmoid(relu(agg2[i] * w2))
// ---------------------------------------------------------------------------
__global__ void epilogue_kernel(const float* __restrict__ w2ptr,
                                float* __restrict__ out, int n) {
    const float w2 = __ldg(w2ptr);
    int i = blockIdx.x * blockDim.x + threadIdx.x;
    int stride = gridDim.x * blockDim.x;
    for (; i < n; i += stride) {
        float h = fmaxf(g_agg2[i] * w2, 0.0f);
        out[i] = 1.0f / (1.0f + __expf(-h));
    }
}

// ---------------------------------------------------------------------------
// kernel_launch: 4 graph-capturable launches, allocation-free.
// Inputs: x [N,1] f32, edge_index [2,E] int32 (JAX-downcast), w1 f32, w2 f32
// ---------------------------------------------------------------------------
extern "C" void kernel_launch(void* const* d_in, const int* in_sizes, int n_in,
                              void* d_out, int out_size) {
    const float* x = (const float*)d_in[0];
    const int* edge_index = (const int*)d_in[1];
    const float* w1 = (const float*)d_in[2];
    const float* w2 = (const float*)d_in[3];
    float* out = (float*)d_out;

    const int n_nodes = in_sizes[0];             // 1,000,000
    const int n_edges = in_sizes[1] / 2;         // 32,000,000

    const int* src = edge_index;                 // edge_index[0]
    const int* dst = edge_index + n_edges;       // edge_index[1]

    float* agg1;
    float* agg2;
    cudaGetSymbolAddress((void**)&agg1, g_agg1);
    cudaGetSymbolAddress((void**)&agg2, g_agg2);

    // 1) zero scratch
    {
        int threads = 256;
        int blocks = 2048;
        zero_kernel<<<blocks, threads>>>(n_nodes);
    }

    // scatter grid: 4 edges per thread
    int threads = 256;
    long long want = ((long long)n_edges / 4 + threads - 1) / threads;
    int blocks = (int)(want > 1048576LL ? 1048576LL : want);
    if (blocks < 1) blocks = 1;

    // 2) pass 1: agg1[dst] += x[src]
    scatter_kernel<false><<<blocks, threads>>>(src, dst, x, w1, agg1, n_edges);

    // 3) pass 2: agg2[dst] += relu(agg1[src] * w1)
    scatter_kernel<true><<<blocks, threads>>>(src, dst, agg1, w1, agg2, n_edges);

    // 4) epilogue: out = sigmoid(relu(agg2 * w2))
    {
        int eblocks = (n_nodes + threads - 1) / threads;
        if (eblocks > 4096) eblocks = 4096;
        epilogue_kernel<<<eblocks, threads>>>(w2, out, n_nodes);
    }
}